// round 9
// baseline (speedup 1.0000x reference)
#include <cuda_runtime.h>
#include <cuda_fp16.h>
#include <cstdint>
#include <cstddef>

#define NROWS 8192
#define DIN   2048
#define DOUT  2048

#define BM 128
#define BN 128
#define BK 32
#define NCHUNK (DIN / BK)          // 64
#define NT_M (NROWS / BM)          // 64
#define NT_N (DOUT / BN)           // 16

#define PITCH 40                   // halves per smem row (80B) -> conflict-free ldmatrix
#define A_TILE_BYTES (BM * PITCH * 2)            // 10240
#define B_TILE_BYTES (BN * PITCH * 2)            // 10240
#define STAGE_BYTES  (A_TILE_BYTES + B_TILE_BYTES)  // 20480
#define SMEM_TOTAL   (2 * STAGE_BYTES)           // 40960 (x2 CTAs/SM)

__device__ __align__(16) __half g_Ah[(size_t)NROWS * DIN];  // 32 MB
__device__ __align__(16) __half g_Bt[(size_t)DOUT * DIN];   // 8 MB, Bt[n][k]=sign(W[k][n])

static __device__ __forceinline__ uint32_t smem_u32(const void* p) {
    uint32_t a;
    asm("{ .reg .u64 t; cvta.to.shared.u64 t, %1; cvt.u32.u64 %0, t; }" : "=r"(a) : "l"(p));
    return a;
}
static __device__ __forceinline__ uint32_t pack2(float a, float b) {
    __half2 h = __floats2half2_rn(a, b);
    return *reinterpret_cast<uint32_t*>(&h);
}
static __device__ __forceinline__ void cp16(uint32_t dst, const void* src) {
    asm volatile("cp.async.cg.shared.global [%0], [%1], 16;" :: "r"(dst), "l"(src));
}
#define CP_COMMIT() asm volatile("cp.async.commit_group;" ::: "memory")
#define CP_WAIT1()  asm volatile("cp.async.wait_group 1;" ::: "memory")

#define LDSM_X4(r0, r1, r2, r3, addr) \
    asm volatile("ldmatrix.sync.aligned.m8n8.x4.shared.b16 {%0,%1,%2,%3}, [%4];" \
                 : "=r"(r0), "=r"(r1), "=r"(r2), "=r"(r3) : "r"(addr))

#define MMA16816(c, a, b0, b1) \
    asm volatile("mma.sync.aligned.m16n8k16.row.col.f32.f16.f16.f32 " \
                 "{%0,%1,%2,%3}, {%4,%5,%6,%7}, {%8,%9}, {%0,%1,%2,%3};" \
                 : "+f"((c)[0]), "+f"((c)[1]), "+f"((c)[2]), "+f"((c)[3]) \
                 : "r"((a)[0]), "r"((a)[1]), "r"((a)[2]), "r"((a)[3]), \
                   "r"(b0), "r"(b1))

// ---------------- fused prep: blocks [0,8192) = A convert, [8192, 12288) = B binarize/transpose ----
__global__ __launch_bounds__(256) void prep_kernel(const float* __restrict__ A,
                                                   const float* __restrict__ W) {
    __shared__ __half s[32][33];
    if (blockIdx.x < NROWS) {
        // prepA: A fp32 -> fp16 row-major (one row per block)
        const int m = blockIdx.x;
        const size_t i = (size_t)m * DIN + threadIdx.x * 8;
        const float4* src = reinterpret_cast<const float4*>(A + i);
        float4 f0 = src[0], f1 = src[1];
        uint4 u;
        u.x = pack2(f0.x, f0.y); u.y = pack2(f0.z, f0.w);
        u.z = pack2(f1.x, f1.y); u.w = pack2(f1.z, f1.w);
        *reinterpret_cast<uint4*>(g_Ah + i) = u;
    } else {
        // prepB: Bt[n][k] = sign(W[k][n]) via 32x32 smem transpose
        const int bid = (int)blockIdx.x - NROWS;
        const int nb = bid % (DOUT / 32);
        const int kb = bid / (DOUT / 32);
        const int tx = threadIdx.x & 31, ty = threadIdx.x >> 5;
        #pragma unroll
        for (int j = 0; j < 4; j++) {
            const int kk = ty + j * 8;
            const float w = W[(size_t)(kb * 32 + kk) * DOUT + nb * 32 + tx];
            s[kk][tx] = __float2half_rn(w > 0.f ? 1.f : (w < 0.f ? -1.f : 0.f));
        }
        __syncthreads();
        #pragma unroll
        for (int j = 0; j < 4; j++) {
            const int nn = ty + j * 8;
            g_Bt[(size_t)(nb * 32 + nn) * DIN + kb * 32 + tx] = s[tx][nn];
        }
    }
}

// -------------------------------- GEMM --------------------------------
// 128x128 tile, 8 warps (4m x 2n), warp tile 32x64, 2-stage cp.async,
// A-frags preloaded for both k-halves + B-frag register double-buffering.
__global__ __launch_bounds__(256, 2) void gemm_kernel(const float* __restrict__ bias,
                                                      float* __restrict__ out) {
    extern __shared__ __align__(16) unsigned char smem[];
    const uint32_t sbase = smem_u32(smem);

    const int tid = threadIdx.x;
    const int lid = tid & 31;
    const int warp = tid >> 5;
    const int warp_m = warp & 3;      // 4 warps in m
    const int warp_n = warp >> 2;     // 2 warps in n
    const int mt = (int)blockIdx.x & 63;
    const int nt = (int)blockIdx.x >> 6;
    const int m0 = mt * BM, n0 = nt * BN;

    // ldmatrix frag base addresses (stage 0)
    const int g = lid >> 3, lr = lid & 7;
    uint32_t a_addr[2][2], b_addr[4][2];
    #pragma unroll
    for (int mf = 0; mf < 2; mf++)
        #pragma unroll
        for (int kh = 0; kh < 2; kh++) {
            const int row = warp_m * 32 + mf * 16 + (g & 1) * 8 + lr;
            const int col = kh * 16 + (g >> 1) * 8;
            a_addr[mf][kh] = sbase + (uint32_t)(row * PITCH + col) * 2;
        }
    #pragma unroll
    for (int nf2 = 0; nf2 < 4; nf2++)
        #pragma unroll
        for (int kh = 0; kh < 2; kh++) {
            const int row = warp_n * 64 + nf2 * 16 + (g >> 1) * 8 + lr;
            const int col = kh * 16 + (g & 1) * 8;
            b_addr[nf2][kh] = sbase + A_TILE_BYTES + (uint32_t)(row * PITCH + col) * 2;
        }

    float c[2][8][4];
    #pragma unroll
    for (int mf = 0; mf < 2; mf++)
        #pragma unroll
        for (int nf = 0; nf < 8; nf++)
            #pragma unroll
            for (int q = 0; q < 4; q++) c[mf][nf][q] = 0.f;

    const __half* gA = g_Ah + (size_t)m0 * DIN;
    const __half* gB = g_Bt + (size_t)n0 * DIN;

    // cp.async mapping: 1024 16B-chunks per stage (A:512, B:512), 4 per thread
    auto issue_stage = [&](int stage, int kbase) {
        const uint32_t so = (uint32_t)stage * STAGE_BYTES;
        #pragma unroll
        for (int j = 0; j < 4; j++) {
            const int cidx = tid + j * 256;
            const bool bB = cidx >= 512;
            const int local = bB ? (cidx - 512) : cidx;
            const int row = local >> 2, seg = local & 3;
            const uint32_t dst = sbase + so + (bB ? A_TILE_BYTES : 0u) +
                                 (uint32_t)(row * PITCH + seg * 8) * 2;
            const __half* src = (bB ? gB : gA) + (size_t)row * DIN + kbase + seg * 8;
            cp16(dst, src);
        }
    };

    issue_stage(0, 0);
    CP_COMMIT();

    for (int kc = 0; kc < NCHUNK; kc++) {
        const int buf = kc & 1;
        if (kc + 1 < NCHUNK) issue_stage((kc + 1) & 1, (kc + 1) * BK);
        CP_COMMIT();
        CP_WAIT1();
        __syncthreads();

        const uint32_t boff = (uint32_t)buf * STAGE_BYTES;

        // preload ALL A fragments for both k-halves
        uint32_t a[2][2][4];
        #pragma unroll
        for (int kh = 0; kh < 2; kh++) {
            LDSM_X4(a[kh][0][0], a[kh][0][1], a[kh][0][2], a[kh][0][3],
                    a_addr[0][kh] + boff);
            LDSM_X4(a[kh][1][0], a[kh][1][1], a[kh][1][2], a[kh][1][3],
                    a_addr[1][kh] + boff);
        }

        // B fragments, register double-buffered with one-burst lookahead
        uint32_t bb[2][4];
        LDSM_X4(bb[0][0], bb[0][1], bb[0][2], bb[0][3], b_addr[0][0] + boff);
        #pragma unroll
        for (int step = 0; step < 8; step++) {
            const int kh = step >> 2, nf2 = step & 3;
            const int cur = step & 1;
            if (step < 7) {
                const int ns = step + 1;
                LDSM_X4(bb[cur ^ 1][0], bb[cur ^ 1][1], bb[cur ^ 1][2], bb[cur ^ 1][3],
                        b_addr[ns & 3][ns >> 2] + boff);
            }
            MMA16816(c[0][nf2 * 2 + 0], a[kh][0], bb[cur][0], bb[cur][1]);
            MMA16816(c[1][nf2 * 2 + 0], a[kh][1], bb[cur][0], bb[cur][1]);
            MMA16816(c[0][nf2 * 2 + 1], a[kh][0], bb[cur][2], bb[cur][3]);
            MMA16816(c[1][nf2 * 2 + 1], a[kh][1], bb[cur][2], bb[cur][3]);
        }
        __syncthreads();
    }

    // epilogue: bias + sector-aligned float2 stores
    #pragma unroll
    for (int nf = 0; nf < 8; nf++) {
        const int col = n0 + warp_n * 64 + nf * 8 + (lid & 3) * 2;
        const float2 bv = *reinterpret_cast<const float2*>(bias + col);
        #pragma unroll
        for (int mf = 0; mf < 2; mf++) {
            const int r0 = m0 + warp_m * 32 + mf * 16 + (lid >> 2);
            float2 v0 = make_float2(c[mf][nf][0] + bv.x, c[mf][nf][1] + bv.y);
            float2 v1 = make_float2(c[mf][nf][2] + bv.x, c[mf][nf][3] + bv.y);
            *reinterpret_cast<float2*>(out + (size_t)r0 * DOUT + col) = v0;
            *reinterpret_cast<float2*>(out + (size_t)(r0 + 8) * DOUT + col) = v1;
        }
    }
}

extern "C" void kernel_launch(void* const* d_in, const int* in_sizes, int n_in,
                              void* d_out, int out_size) {
    const float* A = (const float*)d_in[0];
    const float* W = (const float*)d_in[1];
    const float* b = (const float*)d_in[2];
    float* out = (float*)d_out;

    cudaFuncSetAttribute(gemm_kernel, cudaFuncAttributeMaxDynamicSharedMemorySize, SMEM_TOTAL);

    prep_kernel<<<NROWS + (DIN / 32) * (DOUT / 32), 256>>>(A, W);
    gemm_kernel<<<NT_M * NT_N, 256, SMEM_TOTAL>>>(b, out);
}

// round 10
// speedup vs baseline: 1.1215x; 1.1215x over previous
#include <cuda_runtime.h>
#include <cuda_fp16.h>
#include <cstdint>
#include <cstddef>

#define NROWS 8192
#define DIN   2048
#define DOUT  2048

#define BM 128
#define BN 128
#define BK 32
#define NCHUNK (DIN / BK)          // 64
#define NT_M (NROWS / BM)          // 64
#define NT_N (DOUT / BN)           // 16
#define NSTAGE 3

#define PITCH 40                   // halves per smem row (80B) -> conflict-free ldmatrix
#define A_TILE_BYTES (BM * PITCH * 2)            // 10240
#define B_TILE_BYTES (BN * PITCH * 2)            // 10240
#define STAGE_BYTES  (A_TILE_BYTES + B_TILE_BYTES)  // 20480
#define SMEM_TOTAL   (NSTAGE * STAGE_BYTES)      // 61440 (x2 CTAs = 122880/SM)

#define MF_STRIDE (16 * PITCH * 2)               // 1280 B per 16-row frag step
#define KH_STRIDE 32                             // 16 halves per k-half

__device__ __align__(16) __half g_Ah[(size_t)NROWS * DIN];  // 32 MB
__device__ __align__(16) __half g_Bt[(size_t)DOUT * DIN];   // 8 MB, Bt[n][k]=sign(W[k][n])

static __device__ __forceinline__ uint32_t smem_u32(const void* p) {
    uint32_t a;
    asm("{ .reg .u64 t; cvta.to.shared.u64 t, %1; cvt.u32.u64 %0, t; }" : "=r"(a) : "l"(p));
    return a;
}
static __device__ __forceinline__ uint32_t pack2(float a, float b) {
    __half2 h = __floats2half2_rn(a, b);
    return *reinterpret_cast<uint32_t*>(&h);
}
static __device__ __forceinline__ void cp16(uint32_t dst, const void* src) {
    asm volatile("cp.async.cg.shared.global [%0], [%1], 16;" :: "r"(dst), "l"(src));
}
#define CP_COMMIT() asm volatile("cp.async.commit_group;" ::: "memory")
#define CP_WAIT1()  asm volatile("cp.async.wait_group 1;" ::: "memory")

#define LDSM_X4(r0, r1, r2, r3, addr) \
    asm volatile("ldmatrix.sync.aligned.m8n8.x4.shared.b16 {%0,%1,%2,%3}, [%4];" \
                 : "=r"(r0), "=r"(r1), "=r"(r2), "=r"(r3) : "r"(addr))

#define MMA16816(c, a, b0, b1) \
    asm volatile("mma.sync.aligned.m16n8k16.row.col.f32.f16.f16.f32 " \
                 "{%0,%1,%2,%3}, {%4,%5,%6,%7}, {%8,%9}, {%0,%1,%2,%3};" \
                 : "+f"((c)[0]), "+f"((c)[1]), "+f"((c)[2]), "+f"((c)[3]) \
                 : "r"((a)[0]), "r"((a)[1]), "r"((a)[2]), "r"((a)[3]), \
                   "r"(b0), "r"(b1))

// ---------------- fused prep ----------------
__global__ __launch_bounds__(256) void prep_kernel(const float* __restrict__ A,
                                                   const float* __restrict__ W) {
    __shared__ __half s[32][33];
    if (blockIdx.x < NROWS) {
        const int m = blockIdx.x;
        const size_t i = (size_t)m * DIN + threadIdx.x * 8;
        const float4* src = reinterpret_cast<const float4*>(A + i);
        float4 f0 = src[0], f1 = src[1];
        uint4 u;
        u.x = pack2(f0.x, f0.y); u.y = pack2(f0.z, f0.w);
        u.z = pack2(f1.x, f1.y); u.w = pack2(f1.z, f1.w);
        *reinterpret_cast<uint4*>(g_Ah + i) = u;
    } else {
        const int bid = (int)blockIdx.x - NROWS;
        const int nb = bid % (DOUT / 32);
        const int kb = bid / (DOUT / 32);
        const int tx = threadIdx.x & 31, ty = threadIdx.x >> 5;
        #pragma unroll
        for (int j = 0; j < 4; j++) {
            const int kk = ty + j * 8;
            const float w = W[(size_t)(kb * 32 + kk) * DOUT + nb * 32 + tx];
            s[kk][tx] = __float2half_rn(w > 0.f ? 1.f : (w < 0.f ? -1.f : 0.f));
        }
        __syncthreads();
        #pragma unroll
        for (int j = 0; j < 4; j++) {
            const int nn = ty + j * 8;
            g_Bt[(size_t)(nb * 32 + nn) * DIN + kb * 32 + tx] = s[tx][nn];
        }
    }
}

// -------------------------------- GEMM --------------------------------
// 128x128, 8 warps (4m x 2n), 3-stage cp.async, 1 sync/iter, minimal registers
__global__ __launch_bounds__(256, 2) void gemm_kernel(const float* __restrict__ bias,
                                                      float* __restrict__ out) {
    extern __shared__ __align__(16) unsigned char smem[];
    const uint32_t sbase = smem_u32(smem);

    const int tid = threadIdx.x;
    const int lid = tid & 31;
    const int warp = tid >> 5;
    const int warp_m = warp & 3;
    const int warp_n = warp >> 2;
    const int mt = (int)blockIdx.x & 63;
    const int nt = (int)blockIdx.x >> 6;
    const int m0 = mt * BM, n0 = nt * BN;

    // single base address per operand; frag offsets are compile-time constants
    const int g = lid >> 3, lr = lid & 7;
    const uint32_t a_base = sbase +
        (uint32_t)(((warp_m * 32 + (g & 1) * 8 + lr) * PITCH + (g >> 1) * 8) * 2);
    const uint32_t b_base = sbase + A_TILE_BYTES +
        (uint32_t)(((warp_n * 64 + (g >> 1) * 8 + lr) * PITCH + (g & 1) * 8) * 2);

    float c[2][8][4];
    #pragma unroll
    for (int mf = 0; mf < 2; mf++)
        #pragma unroll
        for (int nf = 0; nf < 8; nf++)
            #pragma unroll
            for (int q = 0; q < 4; q++) c[mf][nf][q] = 0.f;

    const __half* gA = g_Ah + (size_t)m0 * DIN;
    const __half* gB = g_Bt + (size_t)n0 * DIN;

    // cp.async: 1024 16B-chunks/stage (A:512, B:512), 4/thread, recomputed from tid
    auto issue_stage = [&](int stage, int kbase) {
        const uint32_t so = (uint32_t)stage * STAGE_BYTES;
        #pragma unroll
        for (int j = 0; j < 4; j++) {
            const int cidx = tid + j * 256;
            const bool bB = cidx >= 512;
            const int local = bB ? (cidx - 512) : cidx;
            const int row = local >> 2, seg = local & 3;
            const uint32_t dst = sbase + so + (bB ? A_TILE_BYTES : 0u) +
                                 (uint32_t)(row * PITCH + seg * 8) * 2;
            const __half* src = (bB ? gB : gA) + (size_t)row * DIN + kbase + seg * 8;
            cp16(dst, src);
        }
    };

    issue_stage(0, 0);
    CP_COMMIT();
    issue_stage(1, BK);
    CP_COMMIT();

    for (int kc = 0; kc < NCHUNK; kc++) {
        const int stage = kc % NSTAGE;
        CP_WAIT1();
        __syncthreads();
        if (kc + 2 < NCHUNK) issue_stage((kc + 2) % NSTAGE, (kc + 2) * BK);
        CP_COMMIT();

        const uint32_t aoff = a_base + (uint32_t)stage * STAGE_BYTES;
        const uint32_t boff = b_base + (uint32_t)stage * STAGE_BYTES;
        #pragma unroll
        for (int kh = 0; kh < 2; kh++) {
            uint32_t a[2][4];
            LDSM_X4(a[0][0], a[0][1], a[0][2], a[0][3],
                    aoff + kh * KH_STRIDE + 0 * MF_STRIDE);
            LDSM_X4(a[1][0], a[1][1], a[1][2], a[1][3],
                    aoff + kh * KH_STRIDE + 1 * MF_STRIDE);
            #pragma unroll
            for (int nf2 = 0; nf2 < 4; nf2++) {
                uint32_t b0, b1, b2, b3;
                LDSM_X4(b0, b1, b2, b3, boff + kh * KH_STRIDE + nf2 * MF_STRIDE);
                MMA16816(c[0][nf2 * 2 + 0], a[0], b0, b1);
                MMA16816(c[1][nf2 * 2 + 0], a[1], b0, b1);
                MMA16816(c[0][nf2 * 2 + 1], a[0], b2, b3);
                MMA16816(c[1][nf2 * 2 + 1], a[1], b2, b3);
            }
        }
    }

    // epilogue: bias + sector-aligned float2 stores
    #pragma unroll
    for (int nf = 0; nf < 8; nf++) {
        const int col = n0 + warp_n * 64 + nf * 8 + (lid & 3) * 2;
        const float2 bv = *reinterpret_cast<const float2*>(bias + col);
        #pragma unroll
        for (int mf = 0; mf < 2; mf++) {
            const int r0 = m0 + warp_m * 32 + mf * 16 + (lid >> 2);
            float2 v0 = make_float2(c[mf][nf][0] + bv.x, c[mf][nf][1] + bv.y);
            float2 v1 = make_float2(c[mf][nf][2] + bv.x, c[mf][nf][3] + bv.y);
            *reinterpret_cast<float2*>(out + (size_t)r0 * DOUT + col) = v0;
            *reinterpret_cast<float2*>(out + (size_t)(r0 + 8) * DOUT + col) = v1;
        }
    }
}

extern "C" void kernel_launch(void* const* d_in, const int* in_sizes, int n_in,
                              void* d_out, int out_size) {
    const float* A = (const float*)d_in[0];
    const float* W = (const float*)d_in[1];
    const float* b = (const float*)d_in[2];
    float* out = (float*)d_out;

    cudaFuncSetAttribute(gemm_kernel, cudaFuncAttributeMaxDynamicSharedMemorySize, SMEM_TOTAL);

    prep_kernel<<<NROWS + (DIN / 32) * (DOUT / 32), 256>>>(A, W);
    gemm_kernel<<<NT_M * NT_N, 256, SMEM_TOTAL>>>(b, out);
}

// round 11
// speedup vs baseline: 1.1888x; 1.0600x over previous
#include <cuda_runtime.h>
#include <cuda_fp16.h>
#include <cstdint>
#include <cstddef>

#define NROWS 8192
#define DIN   2048
#define DOUT  2048

#define BM 128
#define BN 128
#define BK 32
#define NCHUNK (DIN / BK)          // 64
#define NT_M (NROWS / BM)          // 64
#define NT_N (DOUT / BN)           // 16
#define NSTAGE 3

#define PITCH 40                   // halves per smem row (80B) -> conflict-free ldmatrix
#define A_TILE_BYTES (BM * PITCH * 2)            // 10240
#define B_TILE_BYTES (BN * PITCH * 2)            // 10240
#define STAGE_BYTES  (A_TILE_BYTES + B_TILE_BYTES)  // 20480
#define SMEM_TOTAL   (NSTAGE * STAGE_BYTES)      // 61440 (x2 CTAs = 122880/SM)

#define MF_STRIDE (16 * PITCH * 2)               // 1280 B per 16-row frag step
#define KH_STRIDE 32                             // 16 halves per k-half

__device__ __align__(16) __half g_Ah[(size_t)NROWS * DIN];  // 32 MB
__device__ __align__(16) __half g_Bt[(size_t)DOUT * DIN];   // 8 MB, Bt[n][k]=sign(W[k][n])

static __device__ __forceinline__ uint32_t smem_u32(const void* p) {
    uint32_t a;
    asm("{ .reg .u64 t; cvta.to.shared.u64 t, %1; cvt.u32.u64 %0, t; }" : "=r"(a) : "l"(p));
    return a;
}
static __device__ __forceinline__ uint32_t pack2(float a, float b) {
    __half2 h = __floats2half2_rn(a, b);
    return *reinterpret_cast<uint32_t*>(&h);
}
static __device__ __forceinline__ void cp16(uint32_t dst, const void* src) {
    asm volatile("cp.async.cg.shared.global [%0], [%1], 16;" :: "r"(dst), "l"(src));
}
#define CP_COMMIT() asm volatile("cp.async.commit_group;" ::: "memory")
#define CP_WAIT1()  asm volatile("cp.async.wait_group 1;" ::: "memory")

#define LDSM_X4(r0, r1, r2, r3, addr) \
    asm volatile("ldmatrix.sync.aligned.m8n8.x4.shared.b16 {%0,%1,%2,%3}, [%4];" \
                 : "=r"(r0), "=r"(r1), "=r"(r2), "=r"(r3) : "r"(addr))

#define MMA16816(c, a, b0, b1) \
    asm volatile("mma.sync.aligned.m16n8k16.row.col.f32.f16.f16.f32 " \
                 "{%0,%1,%2,%3}, {%4,%5,%6,%7}, {%8,%9}, {%0,%1,%2,%3};" \
                 : "+f"((c)[0]), "+f"((c)[1]), "+f"((c)[2]), "+f"((c)[3]) \
                 : "r"((a)[0]), "r"((a)[1]), "r"((a)[2]), "r"((a)[3]), \
                   "r"(b0), "r"(b1))

// ---------------- fused prep ----------------
__global__ __launch_bounds__(256) void prep_kernel(const float* __restrict__ A,
                                                   const float* __restrict__ W) {
    __shared__ __half s[32][33];
    if (blockIdx.x < NROWS) {
        const int m = blockIdx.x;
        const size_t i = (size_t)m * DIN + threadIdx.x * 8;
        const float4* src = reinterpret_cast<const float4*>(A + i);
        float4 f0 = src[0], f1 = src[1];
        uint4 u;
        u.x = pack2(f0.x, f0.y); u.y = pack2(f0.z, f0.w);
        u.z = pack2(f1.x, f1.y); u.w = pack2(f1.z, f1.w);
        *reinterpret_cast<uint4*>(g_Ah + i) = u;
    } else {
        const int bid = (int)blockIdx.x - NROWS;
        const int nb = bid % (DOUT / 32);
        const int kb = bid / (DOUT / 32);
        const int tx = threadIdx.x & 31, ty = threadIdx.x >> 5;
        #pragma unroll
        for (int j = 0; j < 4; j++) {
            const int kk = ty + j * 8;
            const float w = W[(size_t)(kb * 32 + kk) * DOUT + nb * 32 + tx];
            s[kk][tx] = __float2half_rn(w > 0.f ? 1.f : (w < 0.f ? -1.f : 0.f));
        }
        __syncthreads();
        #pragma unroll
        for (int j = 0; j < 4; j++) {
            const int nn = ty + j * 8;
            g_Bt[(size_t)(nb * 32 + nn) * DIN + kb * 32 + tx] = s[tx][nn];
        }
    }
}

// one kh half-block: 2 A-LDSM + 4x(B-LDSM + 4 MMA), nf2 visit order rotated by NFOFF
template<int NFOFF>
static __device__ __forceinline__ void mma_half(float (&c)[2][8][4],
                                                uint32_t aoff, uint32_t boff, int kh) {
    const uint32_t ak = aoff + (uint32_t)kh * KH_STRIDE;
    const uint32_t bk = boff + (uint32_t)kh * KH_STRIDE;
    uint32_t a0[4], a1[4];
    LDSM_X4(a0[0], a0[1], a0[2], a0[3], ak + 0 * MF_STRIDE);
    LDSM_X4(a1[0], a1[1], a1[2], a1[3], ak + 1 * MF_STRIDE);
    #pragma unroll
    for (int s = 0; s < 4; s++) {
        const int nf2 = (s + NFOFF) & 3;
        uint32_t b0, b1, b2, b3;
        LDSM_X4(b0, b1, b2, b3, bk + nf2 * MF_STRIDE);
        MMA16816(c[0][nf2 * 2 + 0], a0, b0, b1);
        MMA16816(c[1][nf2 * 2 + 0], a1, b0, b1);
        MMA16816(c[0][nf2 * 2 + 1], a0, b2, b3);
        MMA16816(c[1][nf2 * 2 + 1], a1, b2, b3);
    }
}

// -------------------------------- GEMM --------------------------------
// 128x128, 8 warps (4m x 2n), 3-stage cp.async, 1 sync/iter, warp-skewed bursts
__global__ __launch_bounds__(256, 2) void gemm_kernel(const float* __restrict__ bias,
                                                      float* __restrict__ out) {
    extern __shared__ __align__(16) unsigned char smem[];
    const uint32_t sbase = smem_u32(smem);

    const int tid = threadIdx.x;
    const int lid = tid & 31;
    const int warp = tid >> 5;
    const int warp_m = warp & 3;
    const int warp_n = warp >> 2;
    const int mt = (int)blockIdx.x & 63;
    const int nt = (int)blockIdx.x >> 6;
    const int m0 = mt * BM, n0 = nt * BN;

    const int g = lid >> 3, lr = lid & 7;
    const uint32_t a_base = sbase +
        (uint32_t)(((warp_m * 32 + (g & 1) * 8 + lr) * PITCH + (g >> 1) * 8) * 2);
    const uint32_t b_base = sbase + A_TILE_BYTES +
        (uint32_t)(((warp_n * 64 + (g >> 1) * 8 + lr) * PITCH + (g & 1) * 8) * 2);

    float c[2][8][4];
    #pragma unroll
    for (int mf = 0; mf < 2; mf++)
        #pragma unroll
        for (int nf = 0; nf < 8; nf++)
            #pragma unroll
            for (int q = 0; q < 4; q++) c[mf][nf][q] = 0.f;

    const __half* gA = g_Ah + (size_t)m0 * DIN;
    const __half* gB = g_Bt + (size_t)n0 * DIN;

    auto issue_stage = [&](int stage, int kbase) {
        const uint32_t so = (uint32_t)stage * STAGE_BYTES;
        #pragma unroll
        for (int j = 0; j < 4; j++) {
            const int cidx = tid + j * 256;
            const bool bB = cidx >= 512;
            const int local = bB ? (cidx - 512) : cidx;
            const int row = local >> 2, seg = local & 3;
            const uint32_t dst = sbase + so + (bB ? A_TILE_BYTES : 0u) +
                                 (uint32_t)(row * PITCH + seg * 8) * 2;
            const __half* src = (bB ? gB : gA) + (size_t)row * DIN + kbase + seg * 8;
            cp16(dst, src);
        }
    };

    issue_stage(0, 0);
    CP_COMMIT();
    issue_stage(1, BK);
    CP_COMMIT();

    const int kh_first = warp_m & 1;        // kh visit order skew by warp_m parity

    for (int kc = 0; kc < NCHUNK; kc++) {
        const int stage = kc % NSTAGE;
        CP_WAIT1();
        __syncthreads();

        const uint32_t aoff = a_base + (uint32_t)stage * STAGE_BYTES;
        const uint32_t boff = b_base + (uint32_t)stage * STAGE_BYTES;

        if (warp_n == 0) mma_half<0>(c, aoff, boff, kh_first);
        else             mma_half<2>(c, aoff, boff, kh_first);

        // spread the STS burst into the MMA phase
        if (kc + 2 < NCHUNK) issue_stage((kc + 2) % NSTAGE, (kc + 2) * BK);
        CP_COMMIT();

        if (warp_n == 0) mma_half<0>(c, aoff, boff, kh_first ^ 1);
        else             mma_half<2>(c, aoff, boff, kh_first ^ 1);
    }

    // epilogue: bias + sector-aligned float2 stores
    #pragma unroll
    for (int nf = 0; nf < 8; nf++) {
        const int col = n0 + warp_n * 64 + nf * 8 + (lid & 3) * 2;
        const float2 bv = *reinterpret_cast<const float2*>(bias + col);
        #pragma unroll
        for (int mf = 0; mf < 2; mf++) {
            const int r0 = m0 + warp_m * 32 + mf * 16 + (lid >> 2);
            float2 v0 = make_float2(c[mf][nf][0] + bv.x, c[mf][nf][1] + bv.y);
            float2 v1 = make_float2(c[mf][nf][2] + bv.x, c[mf][nf][3] + bv.y);
            *reinterpret_cast<float2*>(out + (size_t)r0 * DOUT + col) = v0;
            *reinterpret_cast<float2*>(out + (size_t)(r0 + 8) * DOUT + col) = v1;
        }
    }
}

extern "C" void kernel_launch(void* const* d_in, const int* in_sizes, int n_in,
                              void* d_out, int out_size) {
    const float* A = (const float*)d_in[0];
    const float* W = (const float*)d_in[1];
    const float* b = (const float*)d_in[2];
    float* out = (float*)d_out;

    cudaFuncSetAttribute(gemm_kernel, cudaFuncAttributeMaxDynamicSharedMemorySize, SMEM_TOTAL);

    prep_kernel<<<NROWS + (DIN / 32) * (DOUT / 32), 256>>>(A, W);
    gemm_kernel<<<NT_M * NT_N, 256, SMEM_TOTAL>>>(b, out);
}